// round 7
// baseline (speedup 1.0000x reference)
#include <cuda_runtime.h>

#define BN   8
#define CN   64
#define HN   256
#define WN   256
#define HP   257
#define WP   257
#define HWN  (HN * WN)          // 65536
#define NPIX (HP * WP)          // 66049
#define LN_EPS 1e-5f
#define NEG_SLOPE 0.01f

// Padded xs plane: logical xs(i,j), i,j in [0,257), stored at [(i+2),(j+2)]
// in a 261-row x 264-stride plane with zero border -> taps need no bounds checks.
#define HPP  261
#define WPP  261
#define WST  264
#define NPAD (HPP * WST)
#define NPOOL (HPP * WPP)       // logical padded pixels per image (261*261)

#define NBLK   65               // ceil(66049/1024) blocks per image
#define NGRID  (NBLK * BN)      // 520 blocks in fused kernel (single wave)

// Scratch (static device globals — allowed)
__device__ float g_cs [BN * HWN];         // channel sum          [8,256,256]
__device__ float g_xsp[BN * NPAD];        // padded pooled sum
__device__ float g_part[BN * NBLK * 2];   // per-block (sum, sumsq)
__device__ unsigned int g_ctr;            // grid-barrier arrival counter

// ---------------------------------------------------------------------------
// 1) Channel sum, float4 vectorized, explicit 8-deep load batching for MLP,
//    streaming (__ldcs) reads since x has zero reuse. 2048 x 64 threads.
//    Thread 0 also resets the fused kernel's barrier counter (stream-ordered).
// ---------------------------------------------------------------------------
__global__ void k_chansum(const float* __restrict__ x) {
    int t = blockIdx.x * 64 + threadIdx.x;           // [0, BN*HWN/4)
    if (t == 0) g_ctr = 0u;
    const int Q = HWN / 4;                            // 16384 float4 per plane
    int b  = t / Q;
    int p4 = t - b * Q;
    const float4* xp = reinterpret_cast<const float4*>(x) + (size_t)b * CN * Q + p4;
    float ax = 0.f, ay = 0.f, az = 0.f, aw = 0.f;
#pragma unroll
    for (int cc = 0; cc < CN; cc += 8) {
        float4 buf[8];
#pragma unroll
        for (int i = 0; i < 8; ++i)
            buf[i] = __ldcs(xp + (size_t)(cc + i) * Q);
#pragma unroll
        for (int i = 0; i < 8; ++i) {
            ax += buf[i].x; ay += buf[i].y; az += buf[i].z; aw += buf[i].w;
        }
    }
    reinterpret_cast<float4*>(g_cs)[t] = make_float4(ax, ay, az, aw);
}

// ---------------------------------------------------------------------------
// Grid barrier helper: block-wide arrive (tid 0) then spin until `target`
// arrivals. Single co-resident wave (launch_bounds guarantees >=4 blocks/SM
// -> capacity 592 >= 520), so the spin cannot deadlock.
// ---------------------------------------------------------------------------
__device__ __forceinline__ void grid_barrier(int tid, unsigned int target) {
    __syncthreads();
    if (tid == 0) {
        __threadfence();                 // publish this block's stores
        atomicAdd(&g_ctr, 1u);
        volatile unsigned int* ctr = &g_ctr;
        while (*ctr < target) { }
    }
    __syncthreads();
    __threadfence();                     // acquire other blocks' stores
}

// ---------------------------------------------------------------------------
// 2) Fused: pool -> barrier -> 16-tap stencil (+ LN partials) -> barrier ->
//    stats + normalize + LeakyReLU.  Grid (NBLK, BN) = 520 blocks x 256 thr.
// ---------------------------------------------------------------------------
__global__ void __launch_bounds__(256, 4)
k_fused(const float* __restrict__ cw, const float* __restrict__ cb,
        float* __restrict__ out) {
    __shared__ float s_w[8];
    __shared__ float s_red[8][2];
    const int tid  = threadIdx.x;
    const int b    = blockIdx.y;
    const int blk  = blockIdx.y * NBLK + blockIdx.x;     // flat block id
    if (tid < 8) s_w[tid] = cw[tid];
    const float bias = __ldg(cb);

    // ---- Phase A: avg_pool(2,s1,p1,count_include_pad) into padded plane ----
    for (int t = blk * 256 + tid; t < BN * NPOOL; t += NGRID * 256) {
        int bb = t / NPOOL;
        int p  = t - bb * NPOOL;
        int pi = p / WPP;
        int pj = p - pi * WPP;
        int i = pi - 2, j = pj - 2;                       // xs coords
        float v = 0.f;
        if ((unsigned)i < (unsigned)HP && (unsigned)j < (unsigned)WP) {
            const float* cs = g_cs + (size_t)bb * HWN;
            float s = 0.f;
            int r0 = i - 1, c0 = j - 1;
            bool vr0 = (unsigned)r0 < (unsigned)HN, vr1 = (unsigned)i < (unsigned)HN;
            bool vc0 = (unsigned)c0 < (unsigned)WN, vc1 = (unsigned)j < (unsigned)WN;
            if (vr0) {
                const float* row = cs + r0 * WN;
                if (vc0) s += row[c0];
                if (vc1) s += row[j];
            }
            if (vr1) {
                const float* row = cs + i * WN;
                if (vc0) s += row[c0];
                if (vc1) s += row[j];
            }
            v = s * 0.25f;
        }
        g_xsp[(size_t)bb * NPAD + pi * WST + pj] = v;
    }

    grid_barrier(tid, NGRID);            // xs plane complete

    // ---- Phase B: stencil + bias, values held in registers ----
    const float* __restrict__ xs = g_xsp + (size_t)b * NPAD;
    float v0 = 0.f, v1 = 0.f, v2 = 0.f, v3 = 0.f;
    float lsum = 0.f, lsq = 0.f;
    const int pbase = blockIdx.x * 1024 + tid;
    {
        float* vv[4] = {&v0, &v1, &v2, &v3};
#pragma unroll
        for (int k = 0; k < 4; ++k) {
            int p = pbase + k * 256;
            if (p < NPIX) {
                int h  = p / WP;
                int wi = p - h * WP;
                const float* c = xs + (h + 2) * WST + (wi + 2);
                float v = bias;
                v += s_w[0] * (__ldg(c + 2 * WST + 2) - __ldg(c - 2 * WST - 2));
                v += s_w[1] * (__ldg(c + 2 * WST + 1) - __ldg(c - 2 * WST - 1));
                v += s_w[2] * (__ldg(c + 2 * WST    ) - __ldg(c - 2 * WST    ));
                v += s_w[3] * (__ldg(c + 2 * WST - 1) - __ldg(c - 2 * WST + 1));
                v += s_w[4] * (__ldg(c + 2 * WST - 2) - __ldg(c - 2 * WST + 2));
                v += s_w[5] * (__ldg(c + 1 * WST - 2) - __ldg(c - 1 * WST + 2));
                v += s_w[6] * (__ldg(c           - 2) - __ldg(c           + 2));
                v += s_w[7] * (__ldg(c - 1 * WST - 2) - __ldg(c + 1 * WST + 2));
                *vv[k] = v;
                lsum += v;
                lsq  += v * v;
            }
        }
    }

    // Deterministic block reduction: warp shuffles, then ordered combine.
#pragma unroll
    for (int o = 16; o > 0; o >>= 1) {
        lsum += __shfl_down_sync(0xffffffffu, lsum, o);
        lsq  += __shfl_down_sync(0xffffffffu, lsq,  o);
    }
    int wid = tid >> 5, lane = tid & 31;
    if (lane == 0) { s_red[wid][0] = lsum; s_red[wid][1] = lsq; }
    __syncthreads();
    if (tid == 0) {
        float a = 0.f, q = 0.f;
#pragma unroll
        for (int w = 0; w < 8; ++w) { a += s_red[w][0]; q += s_red[w][1]; }
        g_part[(b * NBLK + blockIdx.x) * 2 + 0] = a;
        g_part[(b * NBLK + blockIdx.x) * 2 + 1] = q;
    }

    grid_barrier(tid, 2u * NGRID);       // partials complete

    // ---- Phase C: redundant stats (fixed order -> deterministic) + norm ----
    const float* __restrict__ part = g_part + b * NBLK * 2;
    float a = 0.f, q = 0.f;
#pragma unroll 13
    for (int i = 0; i < NBLK; ++i) {
        a += part[i * 2 + 0];
        q += part[i * 2 + 1];
    }
    const float inv_n = 1.0f / (float)NPIX;
    const float mean = a * inv_n;
    const float istd = rsqrtf(q * inv_n - mean * mean + LN_EPS);

    float* __restrict__ o = out + (size_t)b * NPIX;
    {
        float vv[4] = {v0, v1, v2, v3};
#pragma unroll
        for (int k = 0; k < 4; ++k) {
            int p = pbase + k * 256;
            if (p < NPIX) {
                float v = (vv[k] - mean) * istd;
                o[p] = v >= 0.f ? v : NEG_SLOPE * v;
            }
        }
    }
}

// ---------------------------------------------------------------------------

extern "C" void kernel_launch(void* const* d_in, const int* in_sizes, int n_in,
                              void* d_out, int out_size) {
    const float* x  = (const float*)d_in[0];   // [8,64,256,256]
    const float* cw = (const float*)d_in[1];   // [1,8]
    const float* cb = (const float*)d_in[2];   // [1]
    float* out = (float*)d_out;                // [8,1,257,257]
    (void)in_sizes; (void)n_in; (void)out_size;

    k_chansum<<<2048, 64>>>(x);

    dim3 gfused(NBLK, BN);
    k_fused<<<gfused, 256>>>(cw, cb, out);
}

// round 8
// speedup vs baseline: 1.0685x; 1.0685x over previous
#include <cuda_runtime.h>

#define BN   8
#define CN   64
#define HN   256
#define WN   256
#define HP   257
#define WP   257
#define HWN  (HN * WN)          // 65536
#define NPIX (HP * WP)          // 66049
#define LN_EPS 1e-5f
#define NEG_SLOPE 0.01f

// Padded channel-sum plane: cs(h,w) stored at [(h+3)*CST + (w+4)].
// Rows cover cs rows -3..258 (262 rows), cols -4..263 (stride 268, 16B-aligned
// float4 stores since w%4==0 -> offset (h+3)*268 + w+4 is a multiple of 4).
// Border stays zero forever: __device__ globals are zero-initialized and the
// kernel only ever writes the interior. The composed stencil needs rows/cols
// -3..+2 around every output pixel, all inside this plane.
#define CROWS 262
#define CST   268
#define CPLANE (CROWS * CST)

#define NBLK  65                // ceil(66049/1024) blocks per image
#define NGRID (NBLK * BN)       // 520 blocks, single co-resident wave
#define NTHR  256

// Scratch (static device globals — allowed)
__device__ float g_csp[BN * CPLANE];      // padded channel sum (~2.25 MB)
__device__ float g_part[BN * NBLK * 2];   // per-block (sum, sumsq)
__device__ unsigned int g_tkt;            // ticket barrier counter (NEVER reset:
                                          // each launch adds exactly 2*NGRID, so
                                          // it is always a multiple of NGRID at
                                          // launch start -> replay-safe)

// ---------------------------------------------------------------------------
// Ticket grid barrier: monotone counter, target = next multiple of NGRID.
// Single wave -> all blocks resident -> spin cannot deadlock. A block can only
// arrive at barrier n+1 after barrier n released (needs all n-th arrivals), so
// ticket ranges of successive barriers never interleave.
// ---------------------------------------------------------------------------
__device__ __forceinline__ void grid_barrier(int tid) {
    __syncthreads();
    if (tid == 0) {
        __threadfence();                              // publish this block's stores
        unsigned t = atomicAdd(&g_tkt, 1u) + 1u;
        unsigned target = ((t + NGRID - 1u) / NGRID) * NGRID;
        volatile unsigned* c = &g_tkt;
        while (*c < target) { }
    }
    __syncthreads();
    __threadfence();                                  // acquire other blocks' stores
}

// ---------------------------------------------------------------------------
// One persistent kernel: chansum -> barrier -> 36-tap composed stencil
// (+ LN partials) -> barrier -> stats + normalize + LeakyReLU.
// ---------------------------------------------------------------------------
__global__ void __launch_bounds__(NTHR, 4)
k_all(const float* __restrict__ x, const float* __restrict__ cw,
      const float* __restrict__ cb, float* __restrict__ out) {
    __shared__ float s_c6[36];                // composed 6x6 stencil coeffs
    __shared__ float s_tile[10 * CST];        // 10 padded rows (10.5 KB)
    __shared__ float s_red[8][2];

    const int tid = threadIdx.x;
    const int blk = blockIdx.x;

    // ---- Phase 0: channel sum (float4, 8-deep streaming batches) ----
    {
        const int Q4 = HWN / 4;                       // 16384 float4 per plane
        int t = blk * NTHR + tid;                     // 133120 threads >= 131072
        if (t < BN * Q4) {
            int b  = t / Q4;
            int p4 = t - b * Q4;
            const float4* xp = reinterpret_cast<const float4*>(x)
                               + (size_t)b * CN * Q4 + p4;
            float ax = 0.f, ay = 0.f, az = 0.f, aw = 0.f;
#pragma unroll
            for (int cc = 0; cc < CN; cc += 8) {
                float4 buf[8];
#pragma unroll
                for (int i = 0; i < 8; ++i)
                    buf[i] = __ldcs(xp + (size_t)(cc + i) * Q4);
#pragma unroll
                for (int i = 0; i < 8; ++i) {
                    ax += buf[i].x; ay += buf[i].y; az += buf[i].z; aw += buf[i].w;
                }
            }
            int p = p4 * 4;
            int h = p >> 8, w = p & 255;
            *reinterpret_cast<float4*>(
                g_csp + (size_t)b * CPLANE + (h + 3) * CST + (w + 4)) =
                make_float4(ax, ay, az, aw);
        }
    }

    // ---- Composed coefficients: pool(2) o 16-tap shift stencil = 6x6 ----
    // xs-tap (dr,dc,a) expands to cs-taps (dr+u, dc+v), u,v in {-1,0}, 0.25*a.
    if (tid < 36) {
        const signed char tdr[16] = {2,-2, 2,-2, 2,-2, 2,-2, 2,-2, 1,-1, 0,0, -1,1};
        const signed char tdc[16] = {2,-2, 1,-1, 0, 0,-1, 1,-2, 2,-2, 2,-2,2, -2,2};
        const signed char twi[16] = {0, 0, 1, 1, 2, 2, 3, 3, 4, 4, 5, 5, 6,6,  7,7};
        const signed char tsg[16] = {1,-1, 1,-1, 1,-1, 1,-1, 1,-1, 1,-1, 1,-1, 1,-1};
        int r = tid / 6 - 3, c = tid % 6 - 3;
        float acc = 0.f;
        for (int t2 = 0; t2 < 16; ++t2) {
            int ur = r - tdr[t2], uc = c - tdc[t2];
            if ((ur == 0 || ur == -1) && (uc == 0 || uc == -1))
                acc += (float)tsg[t2] * cw[twi[t2]];
        }
        s_c6[tid] = 0.25f * acc;
    }

    grid_barrier(tid);                        // cs plane + s_c6 ready

    // ---- Phase B: 36-tap stencil from smem tile, values kept in registers ----
    const int b   = blk / NBLK;
    const int xb  = blk - b * NBLK;
    const int p0  = xb * 1024;
    const int h0  = p0 / WP;                  // first output row of this block
    const float* __restrict__ plane = g_csp + (size_t)b * CPLANE;

    // Tile = padded rows h0 .. h0+9 (covers taps for output rows h0..h0+4).
    for (int i4 = tid; i4 < 10 * (CST / 4); i4 += NTHR) {
        int r  = i4 / (CST / 4);
        int c4 = i4 - r * (CST / 4);
        int pr = h0 + r;
        float4 v = make_float4(0.f, 0.f, 0.f, 0.f);
        if (pr < CROWS)
            v = *(reinterpret_cast<const float4*>(plane + (size_t)pr * CST) + c4);
        reinterpret_cast<float4*>(s_tile)[r * (CST / 4) + c4] = v;
    }
    __syncthreads();

    const float bias = __ldg(cb);
    float vv[4] = {0.f, 0.f, 0.f, 0.f};
    float lsum = 0.f, lsq = 0.f;
    const int pbase = p0 + tid;
    {
        int   hh[4], jj[4];
        bool  ok[4];
#pragma unroll
        for (int k = 0; k < 4; ++k) {
            int p = pbase + k * 256;
            ok[k] = p < NPIX;
            int h = p / WP;
            hh[k] = h; jj[k] = p - h * WP;
            vv[k] = bias;
        }
        // coeff-outer order: one coeff LDS feeds 4 FMAs (halves LDS traffic)
#pragma unroll
        for (int r = 0; r < 6; ++r) {
#pragma unroll
            for (int c = 0; c < 6; ++c) {
                float cf = s_c6[r * 6 + c];
#pragma unroll
                for (int k = 0; k < 4; ++k)
                    if (ok[k])
                        vv[k] = fmaf(cf,
                                     s_tile[(hh[k] - h0 + r) * CST + jj[k] + 1 + c],
                                     vv[k]);
            }
        }
#pragma unroll
        for (int k = 0; k < 4; ++k)
            if (ok[k]) { lsum += vv[k]; lsq += vv[k] * vv[k]; }
    }

    // Deterministic block reduction
#pragma unroll
    for (int o = 16; o > 0; o >>= 1) {
        lsum += __shfl_down_sync(0xffffffffu, lsum, o);
        lsq  += __shfl_down_sync(0xffffffffu, lsq,  o);
    }
    int wid = tid >> 5, lane = tid & 31;
    if (lane == 0) { s_red[wid][0] = lsum; s_red[wid][1] = lsq; }
    __syncthreads();
    if (tid == 0) {
        float a = 0.f, q = 0.f;
#pragma unroll
        for (int w = 0; w < 8; ++w) { a += s_red[w][0]; q += s_red[w][1]; }
        g_part[(b * NBLK + xb) * 2 + 0] = a;
        g_part[(b * NBLK + xb) * 2 + 1] = q;
    }

    grid_barrier(tid);                        // partials ready

    // ---- Phase C: redundant deterministic stats + normalize + LeakyReLU ----
    const float* __restrict__ part = g_part + b * NBLK * 2;
    float a = 0.f, q = 0.f;
#pragma unroll 13
    for (int i = 0; i < NBLK; ++i) {
        a += part[i * 2 + 0];
        q += part[i * 2 + 1];
    }
    const float inv_n = 1.0f / (float)NPIX;
    const float mean = a * inv_n;
    const float istd = rsqrtf(q * inv_n - mean * mean + LN_EPS);

    float* __restrict__ o = out + (size_t)b * NPIX;
#pragma unroll
    for (int k = 0; k < 4; ++k) {
        int p = pbase + k * 256;
        if (p < NPIX) {
            float v = (vv[k] - mean) * istd;
            o[p] = v >= 0.f ? v : NEG_SLOPE * v;
        }
    }
}

// ---------------------------------------------------------------------------

extern "C" void kernel_launch(void* const* d_in, const int* in_sizes, int n_in,
                              void* d_out, int out_size) {
    const float* x  = (const float*)d_in[0];   // [8,64,256,256]
    const float* cw = (const float*)d_in[1];   // [1,8]
    const float* cb = (const float*)d_in[2];   // [1]
    float* out = (float*)d_out;                // [8,1,257,257]
    (void)in_sizes; (void)n_in; (void)out_size;

    k_all<<<NGRID, NTHR>>>(x, cw, cb, out);
}